// round 16
// baseline (speedup 1.0000x reference)
#include <cuda_runtime.h>
#include <cstdint>
#include <math.h>

// CBOW negative-sampling loss.
//   d_in[0]: in_embed  float32 [100000, 128]
//   d_in[1]: out_embed float32 [100000, 128]
//   d_in[2]: context   int32   [B, 8]
//   d_in[3]: target    int32   [B]
//   d_in[4]: negatives int32   [B, 10]
// Output: float32 [B]
//
// Round 16: R15 (best: 16.99us) with ONE change — __launch_bounds__(128, 10)
// (reg budget 51 vs 56). Rationale: the R15 __ldcs demotion shifted ctx-row
// loads toward DRAM latency (~577cyc vs ~250), raising latency-coverage
// demand; occ was 46% at 9 CTAs/SM. 51 regs is the untested midpoint between
// 56 (R14/R15, good per-warp MLP) and 40 (R7, MLP collapsed). Single-variable
// test of the reg/occupancy curve at the new operating point.
//
// Established: random 512B gather service (~4.2TB/s DRAM-side) is the wall;
// evict_last protection inert, __ldcs demotion honored (in_embed demoted ->
// out_embed stays L2-resident across graph replays).

#define CTX 8
#define NEG 10
#define D   128

__device__ __forceinline__ float log_sigmoid_fast(float x) {
    return fminf(x, 0.0f) - __logf(1.0f + __expf(-fabsf(x)));
}

__device__ __forceinline__ float dot4(float4 a, float4 b) {
    return a.x * b.x + a.y * b.y + a.z * b.z + a.w * b.w;
}

__global__ __launch_bounds__(128, 10) void cbow_neg_kernel(
    const float* __restrict__ in_embed,
    const float* __restrict__ out_embed,
    const int*   __restrict__ context,
    const int*   __restrict__ target,
    const int*   __restrict__ negatives,
    float*       __restrict__ out,
    int B)
{
    const int lane   = threadIdx.x & 31;
    const int warpId = (blockIdx.x * blockDim.x + threadIdx.x) >> 5;
    const int group  = lane >> 4;            // 0..1: element within warp
    const int sub    = lane & 15;            // 0..15: lane within group
    const int e      = warpId * 2 + group;   // batch element
    if (e >= B) return;                      // B even, warp-uniform exit

    // ---- context indices (vectorized: 2x int4) ----
    const int4 c0 = __ldg(reinterpret_cast<const int4*>(context + e * CTX));
    const int4 c1 = __ldg(reinterpret_cast<const int4*>(context + e * CTX) + 1);
    const int cidx[CTX] = {c0.x, c0.y, c0.z, c0.w, c1.x, c1.y, c1.z, c1.w};

    // ---- v = mean of 8 context rows (STREAMING loads: evict-first) ----
    float4 v0, v1;
    {
        const float4* r = reinterpret_cast<const float4*>(
                              in_embed + (size_t)cidx[0] * D);
        v0 = __ldcs(r + sub);
        v1 = __ldcs(r + sub + 16);
    }
    #pragma unroll
    for (int c = 1; c < CTX; c++) {
        const float4* r = reinterpret_cast<const float4*>(
                              in_embed + (size_t)cidx[c] * D);
        const float4 a = __ldcs(r + sub);
        const float4 b = __ldcs(r + sub + 16);
        v0.x += a.x; v0.y += a.y; v0.z += a.z; v0.w += a.w;
        v1.x += b.x; v1.y += b.y; v1.z += b.z; v1.w += b.w;
    }
    const float inv = 1.0f / (float)CTX;
    v0.x *= inv; v0.y *= inv; v0.z *= inv; v0.w *= inv;
    v1.x *= inv; v1.y *= inv; v1.z *= inv; v1.w *= inv;

    // ---- u-row indices (vectorized; short liveness) ----
    int ridx[NEG + 1];
    ridx[0] = __ldg(&target[e]);
    {
        const int2* np = reinterpret_cast<const int2*>(negatives + e * NEG);
        const int2 n01 = __ldg(np);
        const int2 n23 = __ldg(np + 1);
        const int2 n45 = __ldg(np + 2);
        const int2 n67 = __ldg(np + 3);
        const int2 n89 = __ldg(np + 4);
        ridx[1] = n01.x; ridx[2]  = n01.y; ridx[3] = n23.x; ridx[4]  = n23.y;
        ridx[5] = n45.x; ridx[6]  = n45.y; ridx[7] = n67.x; ridx[8]  = n67.y;
        ridx[9] = n89.x; ridx[10] = n89.y;
    }

    // ---- 11 dots, depth-2 pipelined u-row loads (default caching) ----
    float s[NEG + 1];
    {
        const float4* u0 = reinterpret_cast<const float4*>(
                               out_embed + (size_t)ridx[0] * D);
        float4 a = __ldg(u0 + sub);
        float4 b = __ldg(u0 + sub + 16);
        #pragma unroll
        for (int i = 0; i < NEG; i++) {
            const float4* un = reinterpret_cast<const float4*>(
                                   out_embed + (size_t)ridx[i + 1] * D);
            const float4 an = __ldg(un + sub);       // issue next pair
            const float4 bn = __ldg(un + sub + 16);  // before consuming current
            s[i] = dot4(v0, a) + dot4(v1, b);
            a = an; b = bn;
        }
        s[NEG] = dot4(v0, a) + dot4(v1, b);
    }

    // ---- reduce each score within the 16-lane group (4 stages) ----
    #pragma unroll
    for (int i = 0; i < NEG + 1; i++) {
        float x = s[i];
        x += __shfl_xor_sync(0xffffffffu, x, 8);
        x += __shfl_xor_sync(0xffffffffu, x, 4);
        x += __shfl_xor_sync(0xffffffffu, x, 2);
        x += __shfl_xor_sync(0xffffffffu, x, 1);
        s[i] = x;
    }

    // ---- epilogue: 2 group leaders per warp in parallel lanes ----
    if (sub == 0) {
        float acc = log_sigmoid_fast(s[0]);
        #pragma unroll
        for (int k = 0; k < NEG; k++)
            acc += log_sigmoid_fast(-s[1 + k]);
        out[e] = -acc;
    }
}

extern "C" void kernel_launch(void* const* d_in, const int* in_sizes, int n_in,
                              void* d_out, int out_size)
{
    const float* in_embed  = (const float*)d_in[0];
    const float* out_embed = (const float*)d_in[1];
    const int*   context   = (const int*)d_in[2];
    const int*   target    = (const int*)d_in[3];
    const int*   negatives = (const int*)d_in[4];
    float*       out       = (float*)d_out;

    const int B = out_size;                       // 16384
    const int warps = (B + 1) / 2;                // 2 elements per warp
    const int threads = 128;                      // 4 warps/block
    const int blocks = (warps * 32 + threads - 1) / threads;   // 2048
    cbow_neg_kernel<<<blocks, threads>>>(in_embed, out_embed, context, target,
                                         negatives, out, B);
}

// round 17
// speedup vs baseline: 1.0729x; 1.0729x over previous
#include <cuda_runtime.h>
#include <cstdint>
#include <math.h>

// CBOW negative-sampling loss.
//   d_in[0]: in_embed  float32 [100000, 128]
//   d_in[1]: out_embed float32 [100000, 128]
//   d_in[2]: context   int32   [B, 8]
//   d_in[3]: target    int32   [B]
//   d_in[4]: negatives int32   [B, 10]
// Output: float32 [B]
//
// Round 17: R15 baseline (16.99us: 2 elem/warp, 16-lane groups, __ldcs
// demotion of in_embed) + depth-2 pipelined ctx-mean loop, paid for with
// minblocks 9 -> 8 (reg budget 56 -> 64). Rationale: after demotion the
// ctx rows carry DRAM-class latency through a serial accumulate chain
// while the u-loop is already depth-2; this evens the pipeline. R16
// re-proved that squeezing the reg budget collapses per-warp MLP (worth
// more than warps in the 29-36/SM band), so the budget is RAISED here.

#define CTX 8
#define NEG 10
#define D   128

__device__ __forceinline__ float log_sigmoid_fast(float x) {
    return fminf(x, 0.0f) - __logf(1.0f + __expf(-fabsf(x)));
}

__device__ __forceinline__ float dot4(float4 a, float4 b) {
    return a.x * b.x + a.y * b.y + a.z * b.z + a.w * b.w;
}

__global__ __launch_bounds__(128, 8) void cbow_neg_kernel(
    const float* __restrict__ in_embed,
    const float* __restrict__ out_embed,
    const int*   __restrict__ context,
    const int*   __restrict__ target,
    const int*   __restrict__ negatives,
    float*       __restrict__ out,
    int B)
{
    const int lane   = threadIdx.x & 31;
    const int warpId = (blockIdx.x * blockDim.x + threadIdx.x) >> 5;
    const int group  = lane >> 4;            // 0..1: element within warp
    const int sub    = lane & 15;            // 0..15: lane within group
    const int e      = warpId * 2 + group;   // batch element
    if (e >= B) return;                      // B even, warp-uniform exit

    // ---- context indices (vectorized: 2x int4) ----
    const int4 c0 = __ldg(reinterpret_cast<const int4*>(context + e * CTX));
    const int4 c1 = __ldg(reinterpret_cast<const int4*>(context + e * CTX) + 1);
    const int cidx[CTX] = {c0.x, c0.y, c0.z, c0.w, c1.x, c1.y, c1.z, c1.w};

    // ---- v = mean of 8 ctx rows; STREAMING loads, depth-2 pipelined ----
    float4 v0, v1;
    {
        const float4* r0 = reinterpret_cast<const float4*>(
                               in_embed + (size_t)cidx[0] * D);
        float4 a = __ldcs(r0 + sub);
        float4 b = __ldcs(r0 + sub + 16);
        v0 = make_float4(0.f, 0.f, 0.f, 0.f);
        v1 = make_float4(0.f, 0.f, 0.f, 0.f);
        #pragma unroll
        for (int c = 0; c < CTX - 1; c++) {
            const float4* rn = reinterpret_cast<const float4*>(
                                   in_embed + (size_t)cidx[c + 1] * D);
            const float4 an = __ldcs(rn + sub);       // issue next row's pair
            const float4 bn = __ldcs(rn + sub + 16);  // before accumulating
            v0.x += a.x; v0.y += a.y; v0.z += a.z; v0.w += a.w;
            v1.x += b.x; v1.y += b.y; v1.z += b.z; v1.w += b.w;
            a = an; b = bn;
        }
        v0.x += a.x; v0.y += a.y; v0.z += a.z; v0.w += a.w;
        v1.x += b.x; v1.y += b.y; v1.z += b.z; v1.w += b.w;
    }
    const float inv = 1.0f / (float)CTX;
    v0.x *= inv; v0.y *= inv; v0.z *= inv; v0.w *= inv;
    v1.x *= inv; v1.y *= inv; v1.z *= inv; v1.w *= inv;

    // ---- u-row indices (vectorized; short liveness) ----
    int ridx[NEG + 1];
    ridx[0] = __ldg(&target[e]);
    {
        const int2* np = reinterpret_cast<const int2*>(negatives + e * NEG);
        const int2 n01 = __ldg(np);
        const int2 n23 = __ldg(np + 1);
        const int2 n45 = __ldg(np + 2);
        const int2 n67 = __ldg(np + 3);
        const int2 n89 = __ldg(np + 4);
        ridx[1] = n01.x; ridx[2]  = n01.y; ridx[3] = n23.x; ridx[4]  = n23.y;
        ridx[5] = n45.x; ridx[6]  = n45.y; ridx[7] = n67.x; ridx[8]  = n67.y;
        ridx[9] = n89.x; ridx[10] = n89.y;
    }

    // ---- 11 dots, depth-2 pipelined u-row loads (default caching) ----
    float s[NEG + 1];
    {
        const float4* u0 = reinterpret_cast<const float4*>(
                               out_embed + (size_t)ridx[0] * D);
        float4 a = __ldg(u0 + sub);
        float4 b = __ldg(u0 + sub + 16);
        #pragma unroll
        for (int i = 0; i < NEG; i++) {
            const float4* un = reinterpret_cast<const float4*>(
                                   out_embed + (size_t)ridx[i + 1] * D);
            const float4 an = __ldg(un + sub);       // issue next pair
            const float4 bn = __ldg(un + sub + 16);  // before consuming current
            s[i] = dot4(v0, a) + dot4(v1, b);
            a = an; b = bn;
        }
        s[NEG] = dot4(v0, a) + dot4(v1, b);
    }

    // ---- reduce each score within the 16-lane group (4 stages) ----
    #pragma unroll
    for (int i = 0; i < NEG + 1; i++) {
        float x = s[i];
        x += __shfl_xor_sync(0xffffffffu, x, 8);
        x += __shfl_xor_sync(0xffffffffu, x, 4);
        x += __shfl_xor_sync(0xffffffffu, x, 2);
        x += __shfl_xor_sync(0xffffffffu, x, 1);
        s[i] = x;
    }

    // ---- epilogue: 2 group leaders per warp in parallel lanes ----
    if (sub == 0) {
        float acc = log_sigmoid_fast(s[0]);
        #pragma unroll
        for (int k = 0; k < NEG; k++)
            acc += log_sigmoid_fast(-s[1 + k]);
        out[e] = -acc;
    }
}

extern "C" void kernel_launch(void* const* d_in, const int* in_sizes, int n_in,
                              void* d_out, int out_size)
{
    const float* in_embed  = (const float*)d_in[0];
    const float* out_embed = (const float*)d_in[1];
    const int*   context   = (const int*)d_in[2];
    const int*   target    = (const int*)d_in[3];
    const int*   negatives = (const int*)d_in[4];
    float*       out       = (float*)d_out;

    const int B = out_size;                       // 16384
    const int warps = (B + 1) / 2;                // 2 elements per warp
    const int threads = 128;                      // 4 warps/block
    const int blocks = (warps * 32 + threads - 1) / threads;   // 2048
    cbow_neg_kernel<<<blocks, threads>>>(in_embed, out_embed, context, target,
                                         negatives, out, B);
}